// round 2
// baseline (speedup 1.0000x reference)
#include <cuda_runtime.h>
#include <math.h>

// ---------------------------------------------------------------------------
// Tree-reduce with fused conv gate, fp32, packed f32x2 FMA (Blackwell FFMA2).
//   Per level: lrg[o,l] = sum_{c,k} in[c,2l+k] * W[o,c,k] + b[o]
//   out = l*sig(g) + tanh(r)*(1-sig(g)),  channel groups 512/512/512.
//
// Activations position-major [b][pos][512ch] -> K=1024 contiguous per output.
// W pre-permuted to Wp[o][kk*512+c].
//
// GEMM tile: 128 pos x 32 base-ch (x3 gates), 256 threads.
// Micro-tile: 8 pos x 2 ch x 3 gates, accumulated as 24 packed f32x2 regs.
// x tile stored DUPLICATED in smem ((x,x) pairs) so LDS.128 yields two
// broadcast-packed operands; w loaded as natural packed channel pairs.
// ---------------------------------------------------------------------------

#define BATCH 16
#define CCH   512
#define LMAX  4096
#define KDIM  1024
#define SLAB  8192
#define BM    128     // output positions per block
#define BK    32      // K-tile
#define NROWS 96      // 32 base channels x 3 gate groups
#define XDROW 260     // duplicated x row: 2*BM + pad (16B-aligned stride)

__device__ float g_buf[(size_t)BATCH * SLAB * CCH];   // 268 MB scratch
__device__ float g_wp[1536 * KDIM];                   // permuted W

typedef unsigned long long u64;

__device__ __forceinline__ void ffma2(u64& d, u64 a, u64 b) {
    asm("fma.rn.f32x2 %0, %1, %2, %0;" : "+l"(d) : "l"(a), "l"(b));
}
__device__ __forceinline__ float2 unpk(u64 v) {
    union { u64 u; float2 f; } c; c.u = v; return c.f;
}

// ---------------------------------------------------------------------------
__global__ void permute_w(const float* __restrict__ W) {
    int i = blockIdx.x * blockDim.x + threadIdx.x;
    if (i >= 1536 * KDIM) return;
    int o  = i >> 10;
    int kp = i & 1023;          // kp = kk*512 + c
    int kk = kp >> 9;
    int c  = kp & 511;
    g_wp[i] = W[o * KDIM + c * 2 + kk];
}

// ---------------------------------------------------------------------------
// Transpose h[b][c][j] into position-major layout, splitting destinations:
//   j <  M        -> staging (off_1 region)   [feeds the level-0 partial conv]
//   M <= j < N    -> cur region, position j - M/2   [the raw suffix]
// ---------------------------------------------------------------------------
__global__ void transpose_init(const float* __restrict__ h,
                               const int* __restrict__ Np) {
    __shared__ float tile[32][33];
    int b = blockIdx.z;
    int N = Np[b];
    int s = 31 - __clz(N);
    int Nfp2 = 1 << s;
    int M2 = N - Nfp2;          // M/2
    int M  = 2 * M2;
    int j0 = blockIdx.x * 32;
    int c0 = blockIdx.y * 32;
    if (j0 >= N) return;

    int tx = threadIdx.x & 31, ty = threadIdx.x >> 5;
    const float* hb = h + (size_t)b * CCH * LMAX;
    #pragma unroll
    for (int i = 0; i < 4; i++) {
        int c = c0 + ty + i * 8;
        tile[ty + i * 8][tx] = hb[(size_t)c * LMAX + j0 + tx];
    }
    __syncthreads();
    float* bufb = g_buf + (size_t)b * SLAB * CCH;
    #pragma unroll
    for (int i = 0; i < 4; i++) {
        int j = j0 + ty + i * 8;
        float v = tile[tx][ty + i * 8];
        int c = c0 + tx;
        if (j < M) {
            bufb[(size_t)(4096 + j) * CCH + c] = v;        // staging @ off_1
        } else if (j < N) {
            bufb[(size_t)(j - M2) * CCH + c] = v;          // cur @ off_0
        }
    }
}

// ---------------------------------------------------------------------------
// One conv-reduce level. level==0: partial fold (P = N - Nfp2, input=staging);
// level>=1: tree level (P = (Nfp2 >> (level-1)) / 2).
// ---------------------------------------------------------------------------
__global__ __launch_bounds__(256)
void conv_level(const int* __restrict__ Np, const float* __restrict__ bias,
                int level, int off_in, int off_out, int maxP) {
    int b = blockIdx.z;
    int N = Np[b];
    int s = 31 - __clz(N);
    int Nfp2 = 1 << s;
    int P;
    if (level == 0) {
        P = N - Nfp2;
    } else {
        int len_in = Nfp2 >> (level - 1);
        P = (len_in >= 2) ? (len_in >> 1) : 0;
    }
    int p0 = blockIdx.x * BM;
    if (p0 >= P) return;

    const float* __restrict__ in  = g_buf + ((size_t)b * SLAB + off_in)  * CCH;
    float*       __restrict__ out = g_buf + ((size_t)b * SLAB + off_out) * CCH;
    int cblk = blockIdx.y;   // 0..15

    __shared__ float xsd[BK][XDROW];   // duplicated x: xsd[k][2*pos+{0,1}]
    __shared__ float ws[BK][NROWS];    // W tile [k][g*32 + c]

    int tid = threadIdx.x;
    int tp = tid >> 4;   // 0..15 -> positions tp*8 .. tp*8+7
    int tc = tid & 15;   // channels tc*2, tc*2+1

    u64 acc2[8][3];      // [pos][gate], each packed (ch0, ch1)
    #pragma unroll
    for (int p = 0; p < 8; p++)
        #pragma unroll
        for (int g = 0; g < 3; g++) acc2[p][g] = 0ull;

    // --- global load plans (register-staged prefetch) ---
    // x: 128 pos x 32 k per tile = 1024 float4, 4 per thread
    const float4* xg[4]; int xpos[4], xkq[4];
    #pragma unroll
    for (int a = 0; a < 4; a++) {
        int idx = tid + a * 256;
        int pos = idx >> 3, kq = idx & 7;
        int lc = min(p0 + pos, maxP - 1);
        xg[a]  = (const float4*)(in + (size_t)(2 * lc) * CCH) + kq;
        xpos[a] = pos; xkq[a] = kq;
    }
    // w: 96 rows x 32 k per tile = 768 float4, 3 per thread
    const float4* wg[3]; int wrow[3], wkq[3];
    #pragma unroll
    for (int a = 0; a < 3; a++) {
        int idx = tid + a * 256;
        int row = idx >> 3, kq = idx & 7;
        int grow = (row >> 5) * 512 + cblk * 32 + (row & 31);
        wg[a]  = (const float4*)(g_wp + (size_t)grow * KDIM) + kq;
        wrow[a] = row; wkq[a] = kq;
    }

    float4 xr[4], wr[3];
    #pragma unroll
    for (int a = 0; a < 4; a++) xr[a] = xg[a][0];
    #pragma unroll
    for (int a = 0; a < 3; a++) wr[a] = wg[a][0];

    const int NT = KDIM / BK;   // 32
    for (int t = 0; t < NT; t++) {
        #pragma unroll
        for (int a = 0; a < 4; a++) {
            int k4 = xkq[a] * 4;
            int cx = 2 * xpos[a];
            *(float2*)&xsd[k4 + 0][cx] = make_float2(xr[a].x, xr[a].x);
            *(float2*)&xsd[k4 + 1][cx] = make_float2(xr[a].y, xr[a].y);
            *(float2*)&xsd[k4 + 2][cx] = make_float2(xr[a].z, xr[a].z);
            *(float2*)&xsd[k4 + 3][cx] = make_float2(xr[a].w, xr[a].w);
        }
        #pragma unroll
        for (int a = 0; a < 3; a++) {
            int k4 = wkq[a] * 4;
            ws[k4 + 0][wrow[a]] = wr[a].x;
            ws[k4 + 1][wrow[a]] = wr[a].y;
            ws[k4 + 2][wrow[a]] = wr[a].z;
            ws[k4 + 3][wrow[a]] = wr[a].w;
        }
        __syncthreads();
        if (t + 1 < NT) {
            #pragma unroll
            for (int a = 0; a < 4; a++) xr[a] = xg[a][(t + 1) * 8];
            #pragma unroll
            for (int a = 0; a < 3; a++) wr[a] = wg[a][(t + 1) * 8];
        }
        #pragma unroll 8
        for (int k = 0; k < BK; k++) {
            // 8 duplicated-pair x operands via 4x LDS.128
            ulonglong2 xa = *(const ulonglong2*)&xsd[k][tp * 16 + 0];
            ulonglong2 xb = *(const ulonglong2*)&xsd[k][tp * 16 + 4];
            ulonglong2 xc = *(const ulonglong2*)&xsd[k][tp * 16 + 8];
            ulonglong2 xd = *(const ulonglong2*)&xsd[k][tp * 16 + 12];
            // 3 natural packed channel-pair w operands via LDS.64
            u64 w0 = *(const u64*)&ws[k][ 0 + tc * 2];
            u64 w1 = *(const u64*)&ws[k][32 + tc * 2];
            u64 w2 = *(const u64*)&ws[k][64 + tc * 2];
            u64 xv[8] = {xa.x, xa.y, xb.x, xb.y, xc.x, xc.y, xd.x, xd.y};
            #pragma unroll
            for (int p = 0; p < 8; p++) {
                ffma2(acc2[p][0], xv[p], w0);
                ffma2(acc2[p][1], xv[p], w1);
                ffma2(acc2[p][2], xv[p], w2);
            }
        }
        __syncthreads();
    }

    // --- fused gate epilogue ---
    int chb = cblk * 32 + tc * 2;
    float bl0 = bias[chb],          bl1 = bias[chb + 1];
    float br0 = bias[512 + chb],    br1 = bias[512 + chb + 1];
    float bg0 = bias[1024 + chb],   bg1 = bias[1024 + chb + 1];
    #pragma unroll
    for (int p = 0; p < 8; p++) {
        int l = p0 + tp * 8 + p;
        if (l >= P) continue;
        float2 al = unpk(acc2[p][0]);
        float2 ar = unpk(acc2[p][1]);
        float2 ag = unpk(acc2[p][2]);
        float lv0 = al.x + bl0;
        float lv1 = al.y + bl1;
        float rv0 = tanhf(ar.x + br0);
        float rv1 = tanhf(ar.y + br1);
        float gv0 = 1.0f / (1.0f + expf(-(ag.x + bg0)));
        float gv1 = 1.0f / (1.0f + expf(-(ag.y + bg1)));
        float2 ov;
        ov.x = lv0 * gv0 + rv0 * (1.0f - gv0);
        ov.y = lv1 * gv1 + rv1 * (1.0f - gv1);
        *(float2*)&out[(size_t)l * CCH + chb] = ov;
    }
}

// ---------------------------------------------------------------------------
__global__ void extract(float* __restrict__ out, const int* __restrict__ Np) {
    int b = blockIdx.x;
    int N = Np[b];
    int s = 31 - __clz(N);
    int off = SLAB - (SLAB >> s);
    int c = threadIdx.x;
    out[b * CCH + c] = g_buf[((size_t)b * SLAB + off) * CCH + c];
}

// ---------------------------------------------------------------------------
extern "C" void kernel_launch(void* const* d_in, const int* in_sizes, int n_in,
                              void* d_out, int out_size) {
    const float* h    = (const float*)d_in[0];
    const float* W    = (const float*)d_in[1];
    const float* bias = (const float*)d_in[2];
    const int*   N    = (const int*)d_in[3];
    float* out = (float*)d_out;

    permute_w<<<(1536 * KDIM + 255) / 256, 256>>>(W);

    dim3 tg(LMAX / 32, CCH / 32, BATCH);
    transpose_init<<<tg, 256>>>(h, N);

    // level 0: partial fold of the first M elements (P_b = N - Nfp2 <= 2047)
    {
        int maxP = 2048;
        dim3 g((maxP + BM - 1) / BM, 16, BATCH);
        conv_level<<<g, 256>>>(N, bias, 0, 4096, 0, maxP);
    }

    // tree levels
    int off_in = 0;
    for (int k = 1; k <= 12; k++) {
        int off_out = SLAB - (SLAB >> k);
        int maxP = LMAX >> k;
        dim3 g((maxP + BM - 1) / BM, 16, BATCH);
        conv_level<<<g, 256>>>(N, bias, k, off_in, off_out, maxP);
        off_in = off_out;
    }

    extract<<<BATCH, CCH>>>(out, N);
}